// round 7
// baseline (speedup 1.0000x reference)
#include <cuda_runtime.h>
#include <cuda_bf16.h>
#include <math.h>
#include <stdint.h>

#define BB 8
#define TT 2048
#define DD 1024
#define HH 128
#define MM (BB*TT)

// ---------------- device-global scratch (allocation-guard safe) ------------
__device__ __nv_bfloat16 g_xhi[MM*DD];
__device__ __nv_bfloat16 g_xlo[MM*DD];
__device__ __nv_bfloat16 g_wthi[3*HH*DD];   // W^T [mat][n][k]
__device__ __nv_bfloat16 g_wtlo[3*HH*DD];
__device__ __nv_bfloat16 g_qhi[MM*HH];      // post-RoPE, pre-scaled by 1/sqrt(H)
__device__ __nv_bfloat16 g_qlo[MM*HH];
__device__ __nv_bfloat16 g_khi[MM*HH];      // post-RoPE
__device__ __nv_bfloat16 g_klo[MM*HH];
__device__ __nv_bfloat16 g_vhi[MM*HH];
__device__ __nv_bfloat16 g_vlo[MM*HH];

// ---------------- PTX helpers (base sm_103-safe: no tcgen05!) --------------
__device__ __forceinline__ uint32_t smem_u32(const void* p) {
    uint32_t a;
    asm("{ .reg .u64 t; cvta.to.shared.u64 t, %1; cvt.u32.u64 %0, t; }"
        : "=r"(a) : "l"(p));
    return a;
}

__device__ __forceinline__ void ldsm_x4(uint32_t& a0, uint32_t& a1,
                                        uint32_t& a2, uint32_t& a3, uint32_t addr) {
    asm volatile("ldmatrix.sync.aligned.m8n8.x4.shared.b16 {%0,%1,%2,%3}, [%4];"
                 : "=r"(a0), "=r"(a1), "=r"(a2), "=r"(a3) : "r"(addr));
}
__device__ __forceinline__ void ldsm_x2(uint32_t& b0, uint32_t& b1, uint32_t addr) {
    asm volatile("ldmatrix.sync.aligned.m8n8.x2.shared.b16 {%0,%1}, [%2];"
                 : "=r"(b0), "=r"(b1) : "r"(addr));
}
__device__ __forceinline__ void ldsm_x2t(uint32_t& b0, uint32_t& b1, uint32_t addr) {
    asm volatile("ldmatrix.sync.aligned.m8n8.x2.trans.shared.b16 {%0,%1}, [%2];"
                 : "=r"(b0), "=r"(b1) : "r"(addr));
}

__device__ __forceinline__ void mma16816(float* c, const uint32_t* a,
                                         uint32_t b0, uint32_t b1) {
    asm volatile(
        "mma.sync.aligned.m16n8k16.row.col.f32.bf16.bf16.f32 "
        "{%0,%1,%2,%3}, {%4,%5,%6,%7}, {%8,%9}, {%0,%1,%2,%3};"
        : "+f"(c[0]), "+f"(c[1]), "+f"(c[2]), "+f"(c[3])
        : "r"(a[0]), "r"(a[1]), "r"(a[2]), "r"(a[3]), "r"(b0), "r"(b1));
}

__device__ __forceinline__ uint32_t pack_bf16x2(float a, float b) {
    __nv_bfloat162 h(__float2bfloat16(a), __float2bfloat16(b));  // low=a, high=b
    return *reinterpret_cast<uint32_t*>(&h);
}

// ---------------------------------------------------------------------------
// fp32 -> split bf16 conversions
// ---------------------------------------------------------------------------
__global__ __launch_bounds__(256) void convert_x_kernel(const float* __restrict__ x)
{
    int i = blockIdx.x * 256 + threadIdx.x;          // over MM*DD/4
    float4 v = ((const float4*)x)[i];
    __nv_bfloat16 h0 = __float2bfloat16(v.x);
    __nv_bfloat16 h1 = __float2bfloat16(v.y);
    __nv_bfloat16 h2 = __float2bfloat16(v.z);
    __nv_bfloat16 h3 = __float2bfloat16(v.w);
    float l0 = v.x - __bfloat162float(h0);
    float l1 = v.y - __bfloat162float(h1);
    float l2 = v.z - __bfloat162float(h2);
    float l3 = v.w - __bfloat162float(h3);
    __nv_bfloat162* ph = (__nv_bfloat162*)g_xhi;
    __nv_bfloat162* pl = (__nv_bfloat162*)g_xlo;
    ph[2*i]   = __nv_bfloat162(h0, h1);
    ph[2*i+1] = __nv_bfloat162(h2, h3);
    pl[2*i]   = __nv_bfloat162(__float2bfloat16(l0), __float2bfloat16(l1));
    pl[2*i+1] = __nv_bfloat162(__float2bfloat16(l2), __float2bfloat16(l3));
}

__global__ __launch_bounds__(256) void convert_w_kernel(
    const float* __restrict__ Wq, const float* __restrict__ Wk,
    const float* __restrict__ Wv)
{
    int mat = blockIdx.y;
    const float* __restrict__ W = (mat == 0) ? Wq : ((mat == 1) ? Wk : Wv);
    int i = blockIdx.x * 256 + threadIdx.x;          // 0 .. DD*HH-1
    int k = i >> 7;
    int n = i & 127;
    float w = W[i];
    __nv_bfloat16 h = __float2bfloat16(w);
    float lo = w - __bfloat162float(h);
    size_t o = (size_t)mat * HH * DD + (size_t)n * DD + k;
    g_wthi[o] = h;
    g_wtlo[o] = __float2bfloat16(lo);
}

// ---------------------------------------------------------------------------
// QKV projection via mma.sync split-bf16 + RoPE epilogue, split-bf16 outputs
// (unchanged from round 6)
// ---------------------------------------------------------------------------
#define QP 72

__global__ __launch_bounds__(256) void qkv_mma_kernel()
{
    extern __shared__ __nv_bfloat16 smq[];
    __nv_bfloat16* sxh = smq;
    __nv_bfloat16* sxl = smq + 128*QP;
    __nv_bfloat16* swh = smq + 2*128*QP;
    __nv_bfloat16* swl = smq + 3*128*QP;

    const int tid = threadIdx.x;
    const int w   = tid >> 5;
    const int lane= tid & 31;
    const int mat = blockIdx.y;
    const int m0  = blockIdx.x * 128;

    const __nv_bfloat16* __restrict__ Xh = g_xhi + (size_t)m0 * DD;
    const __nv_bfloat16* __restrict__ Xl = g_xlo + (size_t)m0 * DD;
    const __nv_bfloat16* __restrict__ Bh = g_wthi + (size_t)mat * HH * DD;
    const __nv_bfloat16* __restrict__ Bl = g_wtlo + (size_t)mat * HH * DD;

    float c[16][4];
#pragma unroll
    for (int nt = 0; nt < 16; nt++)
#pragma unroll
        for (int e = 0; e < 4; e++) c[nt][e] = 0.0f;

    for (int kc = 0; kc < 16; kc++) {
        const int kb = kc * 64;
#pragma unroll
        for (int it = 0; it < 4; it++) {
            int idx = it * 256 + tid;
            int row = idx >> 3, seg = idx & 7;
            *(uint4*)(sxh + row*QP + seg*8) = *(const uint4*)(Xh + (size_t)row*DD + kb + seg*8);
        }
#pragma unroll
        for (int it = 0; it < 4; it++) {
            int idx = it * 256 + tid;
            int row = idx >> 3, seg = idx & 7;
            *(uint4*)(sxl + row*QP + seg*8) = *(const uint4*)(Xl + (size_t)row*DD + kb + seg*8);
        }
#pragma unroll
        for (int it = 0; it < 4; it++) {
            int idx = it * 256 + tid;
            int row = idx >> 3, seg = idx & 7;
            *(uint4*)(swh + row*QP + seg*8) = *(const uint4*)(Bh + (size_t)row*DD + kb + seg*8);
        }
#pragma unroll
        for (int it = 0; it < 4; it++) {
            int idx = it * 256 + tid;
            int row = idx >> 3, seg = idx & 7;
            *(uint4*)(swl + row*QP + seg*8) = *(const uint4*)(Bl + (size_t)row*DD + kb + seg*8);
        }
        __syncthreads();

        uint32_t ah[4][4], al[4][4];
        {
            int r = w*16 + (lane & 7) + ((lane >> 3) & 1) * 8;
            int cg = ((lane >> 4) & 1) * 8;
#pragma unroll
            for (int kt = 0; kt < 4; kt++) {
                ldsm_x4(ah[kt][0], ah[kt][1], ah[kt][2], ah[kt][3],
                        smem_u32(sxh + r*QP + kt*16 + cg));
                ldsm_x4(al[kt][0], al[kt][1], al[kt][2], al[kt][3],
                        smem_u32(sxl + r*QP + kt*16 + cg));
            }
        }

#pragma unroll
        for (int nt = 0; nt < 16; nt++) {
#pragma unroll
            for (int kt = 0; kt < 4; kt++) {
                int br = nt*8 + (lane & 7);
                int bc = kt*16 + (lane & 8);
                uint32_t b0, b1, e0, e1;
                ldsm_x2(b0, b1, smem_u32(swh + br*QP + bc));
                ldsm_x2(e0, e1, smem_u32(swl + br*QP + bc));
                mma16816(c[nt], ah[kt], b0, b1);
                mma16816(c[nt], al[kt], b0, b1);
                mma16816(c[nt], ah[kt], e0, e1);
            }
        }
        __syncthreads();
    }

    __nv_bfloat16* oh = (mat == 0) ? g_qhi : (mat == 1) ? g_khi : g_vhi;
    __nv_bfloat16* ol = (mat == 0) ? g_qlo : (mat == 1) ? g_klo : g_vlo;
    const float qs = (mat == 0) ? 0.08838834764831845f : 1.0f;

    const int rloc = w*16 + (lane >> 2);
    const int m_lo = m0 + rloc;
    const int m_hi = m_lo + 8;
    const float pos0 = (float)(m_lo & (TT - 1));
    const float pos1 = (float)(m_hi & (TT - 1));

#pragma unroll
    for (int nt = 0; nt < 16; nt++) {
        int col = nt*8 + (lane & 3)*2;
        float e00 = c[nt][0]*qs, e01 = c[nt][1]*qs;
        float e10 = c[nt][2]*qs, e11 = c[nt][3]*qs;
        if (mat < 2) {
            int p = col >> 1;
            float freq = exp2f(-(float)p * (13.287712379549449f / 64.0f));
            float s0, c0v, s1, c1v;
            sincosf(pos0 * freq, &s0, &c0v);
            sincosf(pos1 * freq, &s1, &c1v);
            float t0 = e00*c0v - e01*s0, t1 = e00*s0 + e01*c0v;
            e00 = t0; e01 = t1;
            t0 = e10*c1v - e11*s1; t1 = e10*s1 + e11*c1v;
            e10 = t0; e11 = t1;
        }
        {
            __nv_bfloat16 h0 = __float2bfloat16(e00), h1 = __float2bfloat16(e01);
            *(uint32_t*)(oh + (size_t)m_lo*HH + col) = pack_bf16x2(__bfloat162float(h0), __bfloat162float(h1));
            *(uint32_t*)(ol + (size_t)m_lo*HH + col) =
                pack_bf16x2(e00 - __bfloat162float(h0), e01 - __bfloat162float(h1));
        }
        {
            __nv_bfloat16 h0 = __float2bfloat16(e10), h1 = __float2bfloat16(e11);
            *(uint32_t*)(oh + (size_t)m_hi*HH + col) = pack_bf16x2(__bfloat162float(h0), __bfloat162float(h1));
            *(uint32_t*)(ol + (size_t)m_hi*HH + col) =
                pack_bf16x2(e10 - __bfloat162float(h0), e11 - __bfloat162float(h1));
        }
    }
}

// ---------------------------------------------------------------------------
// Causal flash attention, balanced pairing + key-split warps.
// grid=(16,8): CTA pa handles i-tiles {pa, 31-pa} (q-tile 64) -> uniform work.
// 256 thr: warp w in 0..3 -> rows 16w..16w+15, keys 0..31 of each j-tile;
//          warp w+4      -> same rows,          keys 32..63.
// Each warp keeps an independent online-softmax stream; streams merged per
// phase through smem. smem: K/V hi/lo tiles 64x128, stride AP=136 (69632 B).
// ---------------------------------------------------------------------------
#define AP 136
#define OP 132

__global__ __launch_bounds__(256) void attn_kernel(float* __restrict__ out)
{
    extern __shared__ __nv_bfloat16 sma[];
    __nv_bfloat16* kh = sma;
    __nv_bfloat16* kl = sma + 64*AP;
    __nv_bfloat16* vh = sma + 2*64*AP;
    __nv_bfloat16* vl = sma + 3*64*AP;
    float* smO = (float*)sma;                 // merge buffer (reused region)
    float* smM = (float*)(sma + 64*OP*2);     // 64 floats
    float* smL = smM + 64;

    const int tid  = threadIdx.x;
    const int w    = tid >> 5;
    const int lane = tid & 31;
    const int half = w >> 2;                  // key half
    const int wr   = w & 3;                   // row group
    const int b    = blockIdx.y;
    const int pa   = blockIdx.x;

    const int rloc = wr*16 + (lane >> 2);

#pragma unroll
    for (int phase = 0; phase < 2; phase++) {
        const int it = (phase == 0) ? pa : (31 - pa);
        const int i0 = it * 64;
        const int ntiles = it + 1;

        // Q fragments for this phase
        const size_t qrow = (size_t)(b*TT + i0 + rloc) * HH;
        uint32_t qh[8][4], ql[8][4];
#pragma unroll
        for (int kt = 0; kt < 8; kt++) {
            int cb = kt*16 + (lane & 3)*2;
            qh[kt][0] = *(const uint32_t*)(g_qhi + qrow + cb);
            qh[kt][1] = *(const uint32_t*)(g_qhi + qrow + 8*HH + cb);
            qh[kt][2] = *(const uint32_t*)(g_qhi + qrow + cb + 8);
            qh[kt][3] = *(const uint32_t*)(g_qhi + qrow + 8*HH + cb + 8);
            ql[kt][0] = *(const uint32_t*)(g_qlo + qrow + cb);
            ql[kt][1] = *(const uint32_t*)(g_qlo + qrow + 8*HH + cb);
            ql[kt][2] = *(const uint32_t*)(g_qlo + qrow + cb + 8);
            ql[kt][3] = *(const uint32_t*)(g_qlo + qrow + 8*HH + cb + 8);
        }

        float o[16][4];
#pragma unroll
        for (int nt = 0; nt < 16; nt++)
#pragma unroll
            for (int e = 0; e < 4; e++) o[nt][e] = 0.0f;
        float mrow0 = -1e30f, mrow1 = -1e30f, l0 = 0.0f, l1 = 0.0f;

        for (int jt = 0; jt < ntiles; jt++) {
            const int j0 = jt * 64;
            __syncthreads();    // smem reuse guard (tiles / merge buffer)

            {
                const size_t gbase = (size_t)(b*TT + j0) * HH;
#pragma unroll
                for (int itr = 0; itr < 4; itr++) {
                    int idx = itr*256 + tid;
                    int row = idx >> 4, seg = idx & 15;
                    *(uint4*)(kh + row*AP + seg*8) = *(const uint4*)(g_khi + gbase + (size_t)row*HH + seg*8);
                }
#pragma unroll
                for (int itr = 0; itr < 4; itr++) {
                    int idx = itr*256 + tid;
                    int row = idx >> 4, seg = idx & 15;
                    *(uint4*)(kl + row*AP + seg*8) = *(const uint4*)(g_klo + gbase + (size_t)row*HH + seg*8);
                }
#pragma unroll
                for (int itr = 0; itr < 4; itr++) {
                    int idx = itr*256 + tid;
                    int row = idx >> 4, seg = idx & 15;
                    *(uint4*)(vh + row*AP + seg*8) = *(const uint4*)(g_vhi + gbase + (size_t)row*HH + seg*8);
                }
#pragma unroll
                for (int itr = 0; itr < 4; itr++) {
                    int idx = itr*256 + tid;
                    int row = idx >> 4, seg = idx & 15;
                    *(uint4*)(vl + row*AP + seg*8) = *(const uint4*)(g_vlo + gbase + (size_t)row*HH + seg*8);
                }
            }
            __syncthreads();

            // S over this warp's 32-key half
            float s[4][4];
#pragma unroll
            for (int nt = 0; nt < 4; nt++)
#pragma unroll
                for (int e = 0; e < 4; e++) s[nt][e] = 0.0f;

#pragma unroll
            for (int nt = 0; nt < 4; nt++) {
#pragma unroll
                for (int kt = 0; kt < 8; kt++) {
                    int br = half*32 + nt*8 + (lane & 7);
                    int bc = kt*16 + (lane & 8);
                    uint32_t b0, b1, e0, e1;
                    ldsm_x2(b0, b1, smem_u32(kh + br*AP + bc));
                    ldsm_x2(e0, e1, smem_u32(kl + br*AP + bc));
                    mma16816(s[nt], qh[kt], b0, b1);
                    mma16816(s[nt], ql[kt], b0, b1);
                    mma16816(s[nt], qh[kt], e0, e1);
                }
            }

            // causal mask on the diagonal tile
            if (jt == ntiles - 1) {
                int row0 = i0 + rloc;
                int row1 = row0 + 8;
#pragma unroll
                for (int nt = 0; nt < 4; nt++) {
                    int colb = j0 + half*32 + nt*8 + (lane & 3)*2;
                    if (colb     > row0) s[nt][0] = -1e30f;
                    if (colb + 1 > row0) s[nt][1] = -1e30f;
                    if (colb     > row1) s[nt][2] = -1e30f;
                    if (colb + 1 > row1) s[nt][3] = -1e30f;
                }
            }

            // per-warp online softmax over its 32 keys
            float rm0 = -1e30f, rm1 = -1e30f;
#pragma unroll
            for (int nt = 0; nt < 4; nt++) {
                rm0 = fmaxf(rm0, fmaxf(s[nt][0], s[nt][1]));
                rm1 = fmaxf(rm1, fmaxf(s[nt][2], s[nt][3]));
            }
            rm0 = fmaxf(rm0, __shfl_xor_sync(0xffffffffu, rm0, 1));
            rm0 = fmaxf(rm0, __shfl_xor_sync(0xffffffffu, rm0, 2));
            rm1 = fmaxf(rm1, __shfl_xor_sync(0xffffffffu, rm1, 1));
            rm1 = fmaxf(rm1, __shfl_xor_sync(0xffffffffu, rm1, 2));

            float mn0 = fmaxf(mrow0, rm0), mn1 = fmaxf(mrow1, rm1);
            float sc0 = __expf(mrow0 - mn0), sc1 = __expf(mrow1 - mn1);
            mrow0 = mn0; mrow1 = mn1;

            float rs0 = 0.0f, rs1 = 0.0f;
            uint32_t ph[2][4], pl[2][4];
#pragma unroll
            for (int nt = 0; nt < 4; nt++) {
                float p0 = __expf(s[nt][0] - mn0);
                float p1 = __expf(s[nt][1] - mn0);
                float p2 = __expf(s[nt][2] - mn1);
                float p3 = __expf(s[nt][3] - mn1);
                rs0 += p0 + p1;
                rs1 += p2 + p3;
                float h0 = __bfloat162float(__float2bfloat16(p0));
                float h1 = __bfloat162float(__float2bfloat16(p1));
                float h2 = __bfloat162float(__float2bfloat16(p2));
                float h3 = __bfloat162float(__float2bfloat16(p3));
                int kt2 = nt >> 1;
                int hi  = (nt & 1) * 2;
                ph[kt2][hi + 0] = pack_bf16x2(h0, h1);
                ph[kt2][hi + 1] = pack_bf16x2(h2, h3);
                pl[kt2][hi + 0] = pack_bf16x2(p0 - h0, p1 - h1);
                pl[kt2][hi + 1] = pack_bf16x2(p2 - h2, p3 - h3);
            }
            rs0 += __shfl_xor_sync(0xffffffffu, rs0, 1);
            rs0 += __shfl_xor_sync(0xffffffffu, rs0, 2);
            rs1 += __shfl_xor_sync(0xffffffffu, rs1, 1);
            rs1 += __shfl_xor_sync(0xffffffffu, rs1, 2);
            l0 = l0 * sc0 + rs0;
            l1 = l1 * sc1 + rs1;

#pragma unroll
            for (int nt = 0; nt < 16; nt++) {
                o[nt][0] *= sc0; o[nt][1] *= sc0;
                o[nt][2] *= sc1; o[nt][3] *= sc1;
            }
#pragma unroll
            for (int nt = 0; nt < 16; nt++) {
#pragma unroll
                for (int kt2 = 0; kt2 < 2; kt2++) {
                    int vr = half*32 + kt2*16 + (lane & 7) + (lane & 8);
                    int vc = nt*8;
                    uint32_t b0, b1, e0, e1;
                    ldsm_x2t(b0, b1, smem_u32(vh + vr*AP + vc));
                    ldsm_x2t(e0, e1, smem_u32(vl + vr*AP + vc));
                    mma16816(o[nt], ph[kt2], b0, b1);
                    mma16816(o[nt], pl[kt2], b0, b1);
                    mma16816(o[nt], ph[kt2], e0, e1);
                }
            }
        }

        // ---- merge the two key-half streams and store ----
        __syncthreads();    // done with K/V tiles; reuse smem as merge buffer
        if (half == 1) {
            if ((lane & 3) == 0) {
                smM[rloc] = mrow0;  smL[rloc] = l0;
                smM[rloc + 8] = mrow1;  smL[rloc + 8] = l1;
            }
#pragma unroll
            for (int nt = 0; nt < 16; nt++) {
                int col = nt*8 + (lane & 3)*2;
                *(float2*)(smO + rloc*OP + col)     = make_float2(o[nt][0], o[nt][1]);
                *(float2*)(smO + (rloc+8)*OP + col) = make_float2(o[nt][2], o[nt][3]);
            }
        }
        __syncthreads();
        if (half == 0) {
            float m2a = smM[rloc],     l2a = smL[rloc];
            float m2b = smM[rloc + 8], l2b = smL[rloc + 8];
            float ms0 = fmaxf(mrow0, m2a), ms1 = fmaxf(mrow1, m2b);
            float ea0 = __expf(mrow0 - ms0), eb0 = __expf(m2a - ms0);
            float ea1 = __expf(mrow1 - ms1), eb1 = __expf(m2b - ms1);
            float inv0 = 1.0f / (l0*ea0 + l2a*eb0);
            float inv1 = 1.0f / (l1*ea1 + l2b*eb1);
            const size_t ob = (size_t)(b*TT + i0 + rloc) * HH;
#pragma unroll
            for (int nt = 0; nt < 16; nt++) {
                int col = nt*8 + (lane & 3)*2;
                float2 o2a = *(float2*)(smO + rloc*OP + col);
                float2 o2b = *(float2*)(smO + (rloc+8)*OP + col);
                float2 v0 = make_float2((o[nt][0]*ea0 + o2a.x*eb0) * inv0,
                                        (o[nt][1]*ea0 + o2a.y*eb0) * inv0);
                float2 v1 = make_float2((o[nt][2]*ea1 + o2b.x*eb1) * inv1,
                                        (o[nt][3]*ea1 + o2b.y*eb1) * inv1);
                *(float2*)(out + ob + col) = v0;
                *(float2*)(out + ob + 8*HH + col) = v1;
            }
        }
    }
}

// ---------------------------------------------------------------------------
extern "C" void kernel_launch(void* const* d_in, const int* in_sizes, int n_in,
                              void* d_out, int out_size)
{
    const float* x  = (const float*)d_in[0];
    const float* Wq = (const float*)d_in[1];
    const float* Wk = (const float*)d_in[2];
    const float* Wv = (const float*)d_in[3];
    float* out = (float*)d_out;

    static int attr_set = 0;
    const int qkv_smem  = 4 * 128 * QP * 2;  // 73728 B
    const int attn_smem = 4 * 64 * AP * 2;   // 69632 B (>= merge buffer 34304 B)
    if (!attr_set) {
        cudaFuncSetAttribute(qkv_mma_kernel,
                             cudaFuncAttributeMaxDynamicSharedMemorySize, qkv_smem);
        cudaFuncSetAttribute(attn_kernel,
                             cudaFuncAttributeMaxDynamicSharedMemorySize, attn_smem);
        attr_set = 1;
    }

    convert_x_kernel<<<MM * DD / 4 / 256, 256>>>(x);
    convert_w_kernel<<<dim3(DD * HH / 256, 3), 256>>>(Wq, Wk, Wv);
    qkv_mma_kernel<<<dim3(MM / 128, 3), 256, qkv_smem>>>();
    attn_kernel<<<dim3(16, BB), 256, attn_smem>>>(out);
}

// round 8
// speedup vs baseline: 1.4188x; 1.4188x over previous
#include <cuda_runtime.h>
#include <cuda_bf16.h>
#include <math.h>
#include <stdint.h>

#define BB 8
#define TT 2048
#define DD 1024
#define HH 128
#define MM (BB*TT)

// ---------------- device-global scratch (allocation-guard safe) ------------
__device__ __nv_bfloat16 g_xhi[MM*DD];
__device__ __nv_bfloat16 g_xlo[MM*DD];
__device__ __nv_bfloat16 g_wthi[3*HH*DD];   // W^T [mat][n][k]
__device__ __nv_bfloat16 g_wtlo[3*HH*DD];
__device__ __nv_bfloat16 g_qhi[MM*HH];      // post-RoPE, pre-scaled by 1/sqrt(H)
__device__ __nv_bfloat16 g_qlo[MM*HH];
__device__ __nv_bfloat16 g_khi[MM*HH];      // post-RoPE
__device__ __nv_bfloat16 g_klo[MM*HH];
__device__ __nv_bfloat16 g_vhi[MM*HH];
__device__ __nv_bfloat16 g_vlo[MM*HH];
// split-KV partials: [z][b*TT+row]
__device__ float g_po[2*MM*HH];
__device__ float g_pm[2*MM];
__device__ float g_pl[2*MM];

// ---------------- PTX helpers (base sm_103-safe: no tcgen05!) --------------
__device__ __forceinline__ uint32_t smem_u32(const void* p) {
    uint32_t a;
    asm("{ .reg .u64 t; cvta.to.shared.u64 t, %1; cvt.u32.u64 %0, t; }"
        : "=r"(a) : "l"(p));
    return a;
}

__device__ __forceinline__ void ldsm_x4(uint32_t& a0, uint32_t& a1,
                                        uint32_t& a2, uint32_t& a3, uint32_t addr) {
    asm volatile("ldmatrix.sync.aligned.m8n8.x4.shared.b16 {%0,%1,%2,%3}, [%4];"
                 : "=r"(a0), "=r"(a1), "=r"(a2), "=r"(a3) : "r"(addr));
}
__device__ __forceinline__ void ldsm_x2(uint32_t& b0, uint32_t& b1, uint32_t addr) {
    asm volatile("ldmatrix.sync.aligned.m8n8.x2.shared.b16 {%0,%1}, [%2];"
                 : "=r"(b0), "=r"(b1) : "r"(addr));
}
__device__ __forceinline__ void ldsm_x2t(uint32_t& b0, uint32_t& b1, uint32_t addr) {
    asm volatile("ldmatrix.sync.aligned.m8n8.x2.trans.shared.b16 {%0,%1}, [%2];"
                 : "=r"(b0), "=r"(b1) : "r"(addr));
}

__device__ __forceinline__ void mma16816(float* c, const uint32_t* a,
                                         uint32_t b0, uint32_t b1) {
    asm volatile(
        "mma.sync.aligned.m16n8k16.row.col.f32.bf16.bf16.f32 "
        "{%0,%1,%2,%3}, {%4,%5,%6,%7}, {%8,%9}, {%0,%1,%2,%3};"
        : "+f"(c[0]), "+f"(c[1]), "+f"(c[2]), "+f"(c[3])
        : "r"(a[0]), "r"(a[1]), "r"(a[2]), "r"(a[3]), "r"(b0), "r"(b1));
}

__device__ __forceinline__ uint32_t pack_bf16x2(float a, float b) {
    __nv_bfloat162 h(__float2bfloat16(a), __float2bfloat16(b));  // low=a, high=b
    return *reinterpret_cast<uint32_t*>(&h);
}

// ---------------------------------------------------------------------------
// fp32 -> split bf16 conversions
// ---------------------------------------------------------------------------
__global__ __launch_bounds__(256) void convert_x_kernel(const float* __restrict__ x)
{
    int i = blockIdx.x * 256 + threadIdx.x;          // over MM*DD/4
    float4 v = ((const float4*)x)[i];
    __nv_bfloat16 h0 = __float2bfloat16(v.x);
    __nv_bfloat16 h1 = __float2bfloat16(v.y);
    __nv_bfloat16 h2 = __float2bfloat16(v.z);
    __nv_bfloat16 h3 = __float2bfloat16(v.w);
    float l0 = v.x - __bfloat162float(h0);
    float l1 = v.y - __bfloat162float(h1);
    float l2 = v.z - __bfloat162float(h2);
    float l3 = v.w - __bfloat162float(h3);
    __nv_bfloat162* ph = (__nv_bfloat162*)g_xhi;
    __nv_bfloat162* pl = (__nv_bfloat162*)g_xlo;
    ph[2*i]   = __nv_bfloat162(h0, h1);
    ph[2*i+1] = __nv_bfloat162(h2, h3);
    pl[2*i]   = __nv_bfloat162(__float2bfloat16(l0), __float2bfloat16(l1));
    pl[2*i+1] = __nv_bfloat162(__float2bfloat16(l2), __float2bfloat16(l3));
}

__global__ __launch_bounds__(256) void convert_w_kernel(
    const float* __restrict__ Wq, const float* __restrict__ Wk,
    const float* __restrict__ Wv)
{
    int mat = blockIdx.y;
    const float* __restrict__ W = (mat == 0) ? Wq : ((mat == 1) ? Wk : Wv);
    int i = blockIdx.x * 256 + threadIdx.x;          // 0 .. DD*HH-1
    int k = i >> 7;
    int n = i & 127;
    float w = W[i];
    __nv_bfloat16 h = __float2bfloat16(w);
    float lo = w - __bfloat162float(h);
    size_t o = (size_t)mat * HH * DD + (size_t)n * DD + k;
    g_wthi[o] = h;
    g_wtlo[o] = __float2bfloat16(lo);
}

// ---------------------------------------------------------------------------
// QKV projection via mma.sync split-bf16 + RoPE epilogue (unchanged, r6)
// ---------------------------------------------------------------------------
#define QP 72

__global__ __launch_bounds__(256) void qkv_mma_kernel()
{
    extern __shared__ __nv_bfloat16 smq[];
    __nv_bfloat16* sxh = smq;
    __nv_bfloat16* sxl = smq + 128*QP;
    __nv_bfloat16* swh = smq + 2*128*QP;
    __nv_bfloat16* swl = smq + 3*128*QP;

    const int tid = threadIdx.x;
    const int w   = tid >> 5;
    const int lane= tid & 31;
    const int mat = blockIdx.y;
    const int m0  = blockIdx.x * 128;

    const __nv_bfloat16* __restrict__ Xh = g_xhi + (size_t)m0 * DD;
    const __nv_bfloat16* __restrict__ Xl = g_xlo + (size_t)m0 * DD;
    const __nv_bfloat16* __restrict__ Bh = g_wthi + (size_t)mat * HH * DD;
    const __nv_bfloat16* __restrict__ Bl = g_wtlo + (size_t)mat * HH * DD;

    float c[16][4];
#pragma unroll
    for (int nt = 0; nt < 16; nt++)
#pragma unroll
        for (int e = 0; e < 4; e++) c[nt][e] = 0.0f;

    for (int kc = 0; kc < 16; kc++) {
        const int kb = kc * 64;
#pragma unroll
        for (int it = 0; it < 4; it++) {
            int idx = it * 256 + tid;
            int row = idx >> 3, seg = idx & 7;
            *(uint4*)(sxh + row*QP + seg*8) = *(const uint4*)(Xh + (size_t)row*DD + kb + seg*8);
        }
#pragma unroll
        for (int it = 0; it < 4; it++) {
            int idx = it * 256 + tid;
            int row = idx >> 3, seg = idx & 7;
            *(uint4*)(sxl + row*QP + seg*8) = *(const uint4*)(Xl + (size_t)row*DD + kb + seg*8);
        }
#pragma unroll
        for (int it = 0; it < 4; it++) {
            int idx = it * 256 + tid;
            int row = idx >> 3, seg = idx & 7;
            *(uint4*)(swh + row*QP + seg*8) = *(const uint4*)(Bh + (size_t)row*DD + kb + seg*8);
        }
#pragma unroll
        for (int it = 0; it < 4; it++) {
            int idx = it * 256 + tid;
            int row = idx >> 3, seg = idx & 7;
            *(uint4*)(swl + row*QP + seg*8) = *(const uint4*)(Bl + (size_t)row*DD + kb + seg*8);
        }
        __syncthreads();

        uint32_t ah[4][4], al[4][4];
        {
            int r = w*16 + (lane & 7) + ((lane >> 3) & 1) * 8;
            int cg = ((lane >> 4) & 1) * 8;
#pragma unroll
            for (int kt = 0; kt < 4; kt++) {
                ldsm_x4(ah[kt][0], ah[kt][1], ah[kt][2], ah[kt][3],
                        smem_u32(sxh + r*QP + kt*16 + cg));
                ldsm_x4(al[kt][0], al[kt][1], al[kt][2], al[kt][3],
                        smem_u32(sxl + r*QP + kt*16 + cg));
            }
        }

#pragma unroll
        for (int nt = 0; nt < 16; nt++) {
#pragma unroll
            for (int kt = 0; kt < 4; kt++) {
                int br = nt*8 + (lane & 7);
                int bc = kt*16 + (lane & 8);
                uint32_t b0, b1, e0, e1;
                ldsm_x2(b0, b1, smem_u32(swh + br*QP + bc));
                ldsm_x2(e0, e1, smem_u32(swl + br*QP + bc));
                mma16816(c[nt], ah[kt], b0, b1);
                mma16816(c[nt], al[kt], b0, b1);
                mma16816(c[nt], ah[kt], e0, e1);
            }
        }
        __syncthreads();
    }

    __nv_bfloat16* oh = (mat == 0) ? g_qhi : (mat == 1) ? g_khi : g_vhi;
    __nv_bfloat16* ol = (mat == 0) ? g_qlo : (mat == 1) ? g_klo : g_vlo;
    const float qs = (mat == 0) ? 0.08838834764831845f : 1.0f;

    const int rloc = w*16 + (lane >> 2);
    const int m_lo = m0 + rloc;
    const int m_hi = m_lo + 8;
    const float pos0 = (float)(m_lo & (TT - 1));
    const float pos1 = (float)(m_hi & (TT - 1));

#pragma unroll
    for (int nt = 0; nt < 16; nt++) {
        int col = nt*8 + (lane & 3)*2;
        float e00 = c[nt][0]*qs, e01 = c[nt][1]*qs;
        float e10 = c[nt][2]*qs, e11 = c[nt][3]*qs;
        if (mat < 2) {
            int p = col >> 1;
            float freq = exp2f(-(float)p * (13.287712379549449f / 64.0f));
            float s0, c0v, s1, c1v;
            sincosf(pos0 * freq, &s0, &c0v);
            sincosf(pos1 * freq, &s1, &c1v);
            float t0 = e00*c0v - e01*s0, t1 = e00*s0 + e01*c0v;
            e00 = t0; e01 = t1;
            t0 = e10*c1v - e11*s1; t1 = e10*s1 + e11*c1v;
            e10 = t0; e11 = t1;
        }
        {
            __nv_bfloat16 h0 = __float2bfloat16(e00), h1 = __float2bfloat16(e01);
            *(uint32_t*)(oh + (size_t)m_lo*HH + col) = pack_bf16x2(__bfloat162float(h0), __bfloat162float(h1));
            *(uint32_t*)(ol + (size_t)m_lo*HH + col) =
                pack_bf16x2(e00 - __bfloat162float(h0), e01 - __bfloat162float(h1));
        }
        {
            __nv_bfloat16 h0 = __float2bfloat16(e10), h1 = __float2bfloat16(e11);
            *(uint32_t*)(oh + (size_t)m_hi*HH + col) = pack_bf16x2(__bfloat162float(h0), __bfloat162float(h1));
            *(uint32_t*)(ol + (size_t)m_hi*HH + col) =
                pack_bf16x2(e10 - __bfloat162float(h0), e11 - __bfloat162float(h1));
        }
    }
}

// ---------------------------------------------------------------------------
// Causal flash attention (round-6 body), 2-way split-KV across gridDim.z.
// grid=(16,8,2): i-tile (reversed), batch, key-half.  256 thr, q-tile 128.
// Each CTA processes its half of the j-tiles and writes unnormalized
// partials (O, m, l) to global scratch; combine_kernel finishes.
// ---------------------------------------------------------------------------
#define AP 136

__global__ __launch_bounds__(256) void attn_kernel()
{
    extern __shared__ __nv_bfloat16 sma[];
    __nv_bfloat16* kh = sma;
    __nv_bfloat16* kl = sma + 64*AP;
    __nv_bfloat16* vh = sma + 2*64*AP;
    __nv_bfloat16* vl = sma + 3*64*AP;

    const int tid = threadIdx.x;
    const int w   = tid >> 5;
    const int lane= tid & 31;
    const int b   = blockIdx.y;
    const int z   = blockIdx.z;
    const int i0  = (gridDim.x - 1 - blockIdx.x) * 128;

    const int rloc = w*16 + (lane >> 2);
    const size_t qrow = (size_t)(b*TT + i0 + rloc) * HH;

    uint32_t qh[8][4], ql[8][4];
#pragma unroll
    for (int kt = 0; kt < 8; kt++) {
        int cb = kt*16 + (lane & 3)*2;
        qh[kt][0] = *(const uint32_t*)(g_qhi + qrow + cb);
        qh[kt][1] = *(const uint32_t*)(g_qhi + qrow + 8*HH + cb);
        qh[kt][2] = *(const uint32_t*)(g_qhi + qrow + cb + 8);
        qh[kt][3] = *(const uint32_t*)(g_qhi + qrow + 8*HH + cb + 8);
        ql[kt][0] = *(const uint32_t*)(g_qlo + qrow + cb);
        ql[kt][1] = *(const uint32_t*)(g_qlo + qrow + 8*HH + cb);
        ql[kt][2] = *(const uint32_t*)(g_qlo + qrow + cb + 8);
        ql[kt][3] = *(const uint32_t*)(g_qlo + qrow + 8*HH + cb + 8);
    }

    float o[16][4];
#pragma unroll
    for (int nt = 0; nt < 16; nt++)
#pragma unroll
        for (int e = 0; e < 4; e++) o[nt][e] = 0.0f;
    float mrow0 = -1e30f, mrow1 = -1e30f, l0 = 0.0f, l1 = 0.0f;

    const int ntiles = i0/64 + 2;            // even
    const int htiles = ntiles >> 1;
    const int jt0 = z * htiles;
    const int jt1 = jt0 + htiles;

    for (int jt = jt0; jt < jt1; jt++) {
        const int j0 = jt * 64;
        __syncthreads();

        {
            const size_t gbase = (size_t)(b*TT + j0) * HH;
#pragma unroll
            for (int it = 0; it < 4; it++) {
                int idx = it*256 + tid;
                int row = idx >> 4, seg = idx & 15;
                *(uint4*)(kh + row*AP + seg*8) = *(const uint4*)(g_khi + gbase + (size_t)row*HH + seg*8);
            }
#pragma unroll
            for (int it = 0; it < 4; it++) {
                int idx = it*256 + tid;
                int row = idx >> 4, seg = idx & 15;
                *(uint4*)(kl + row*AP + seg*8) = *(const uint4*)(g_klo + gbase + (size_t)row*HH + seg*8);
            }
#pragma unroll
            for (int it = 0; it < 4; it++) {
                int idx = it*256 + tid;
                int row = idx >> 4, seg = idx & 15;
                *(uint4*)(vh + row*AP + seg*8) = *(const uint4*)(g_vhi + gbase + (size_t)row*HH + seg*8);
            }
#pragma unroll
            for (int it = 0; it < 4; it++) {
                int idx = it*256 + tid;
                int row = idx >> 4, seg = idx & 15;
                *(uint4*)(vl + row*AP + seg*8) = *(const uint4*)(g_vlo + gbase + (size_t)row*HH + seg*8);
            }
        }
        __syncthreads();

        float s[8][4];
#pragma unroll
        for (int nt = 0; nt < 8; nt++)
#pragma unroll
            for (int e = 0; e < 4; e++) s[nt][e] = 0.0f;

#pragma unroll
        for (int nt = 0; nt < 8; nt++) {
#pragma unroll
            for (int kt = 0; kt < 8; kt++) {
                int br = nt*8 + (lane & 7);
                int bc = kt*16 + (lane & 8);
                uint32_t b0, b1, e0, e1;
                ldsm_x2(b0, b1, smem_u32(kh + br*AP + bc));
                ldsm_x2(e0, e1, smem_u32(kl + br*AP + bc));
                mma16816(s[nt], qh[kt], b0, b1);
                mma16816(s[nt], ql[kt], b0, b1);
                mma16816(s[nt], qh[kt], e0, e1);
            }
        }

        if (j0 >= i0) {
            int row0 = i0 + rloc;
            int row1 = row0 + 8;
#pragma unroll
            for (int nt = 0; nt < 8; nt++) {
                int colb = j0 + nt*8 + (lane & 3)*2;
                if (colb     > row0) s[nt][0] = -1e30f;
                if (colb + 1 > row0) s[nt][1] = -1e30f;
                if (colb     > row1) s[nt][2] = -1e30f;
                if (colb + 1 > row1) s[nt][3] = -1e30f;
            }
        }

        float rm0 = -1e30f, rm1 = -1e30f;
#pragma unroll
        for (int nt = 0; nt < 8; nt++) {
            rm0 = fmaxf(rm0, fmaxf(s[nt][0], s[nt][1]));
            rm1 = fmaxf(rm1, fmaxf(s[nt][2], s[nt][3]));
        }
        rm0 = fmaxf(rm0, __shfl_xor_sync(0xffffffffu, rm0, 1));
        rm0 = fmaxf(rm0, __shfl_xor_sync(0xffffffffu, rm0, 2));
        rm1 = fmaxf(rm1, __shfl_xor_sync(0xffffffffu, rm1, 1));
        rm1 = fmaxf(rm1, __shfl_xor_sync(0xffffffffu, rm1, 2));

        float mn0 = fmaxf(mrow0, rm0), mn1 = fmaxf(mrow1, rm1);
        float sc0 = __expf(mrow0 - mn0), sc1 = __expf(mrow1 - mn1);
        mrow0 = mn0; mrow1 = mn1;

        float rs0 = 0.0f, rs1 = 0.0f;
        uint32_t ph[4][4], pl[4][4];
#pragma unroll
        for (int nt = 0; nt < 8; nt++) {
            float p0 = __expf(s[nt][0] - mn0);
            float p1 = __expf(s[nt][1] - mn0);
            float p2 = __expf(s[nt][2] - mn1);
            float p3 = __expf(s[nt][3] - mn1);
            rs0 += p0 + p1;
            rs1 += p2 + p3;
            float h0 = __bfloat162float(__float2bfloat16(p0));
            float h1 = __bfloat162float(__float2bfloat16(p1));
            float h2 = __bfloat162float(__float2bfloat16(p2));
            float h3 = __bfloat162float(__float2bfloat16(p3));
            int kt2 = nt >> 1;
            int hi  = (nt & 1) * 2;
            ph[kt2][hi + 0] = pack_bf16x2(h0, h1);
            ph[kt2][hi + 1] = pack_bf16x2(h2, h3);
            pl[kt2][hi + 0] = pack_bf16x2(p0 - h0, p1 - h1);
            pl[kt2][hi + 1] = pack_bf16x2(p2 - h2, p3 - h3);
        }
        rs0 += __shfl_xor_sync(0xffffffffu, rs0, 1);
        rs0 += __shfl_xor_sync(0xffffffffu, rs0, 2);
        rs1 += __shfl_xor_sync(0xffffffffu, rs1, 1);
        rs1 += __shfl_xor_sync(0xffffffffu, rs1, 2);
        l0 = l0 * sc0 + rs0;
        l1 = l1 * sc1 + rs1;

#pragma unroll
        for (int nt = 0; nt < 16; nt++) {
            o[nt][0] *= sc0; o[nt][1] *= sc0;
            o[nt][2] *= sc1; o[nt][3] *= sc1;
        }
#pragma unroll
        for (int nt = 0; nt < 16; nt++) {
#pragma unroll
            for (int kt2 = 0; kt2 < 4; kt2++) {
                int vr = kt2*16 + (lane & 7) + (lane & 8);
                int vc = nt*8;
                uint32_t b0, b1, e0, e1;
                ldsm_x2t(b0, b1, smem_u32(vh + vr*AP + vc));
                ldsm_x2t(e0, e1, smem_u32(vl + vr*AP + vc));
                mma16816(o[nt], ph[kt2], b0, b1);
                mma16816(o[nt], pl[kt2], b0, b1);
                mma16816(o[nt], ph[kt2], e0, e1);
            }
        }
    }

    // store unnormalized partials
    const size_t prow = (size_t)z*MM + (size_t)(b*TT + i0 + rloc);
    if ((lane & 3) == 0) {
        g_pm[prow]     = mrow0;  g_pl[prow]     = l0;
        g_pm[prow + 8] = mrow1;  g_pl[prow + 8] = l1;
    }
#pragma unroll
    for (int nt = 0; nt < 16; nt++) {
        int col = nt*8 + (lane & 3)*2;
        *(float2*)(g_po + prow*HH + col)       = make_float2(o[nt][0], o[nt][1]);
        *(float2*)(g_po + (prow + 8)*HH + col) = make_float2(o[nt][2], o[nt][3]);
    }
}

// ---------------------------------------------------------------------------
// combine the two split-KV partials
// ---------------------------------------------------------------------------
__global__ __launch_bounds__(256) void combine_kernel(float* __restrict__ out)
{
    int i = blockIdx.x * 256 + threadIdx.x;          // over MM*HH/4
    int row = i >> 5;                                 // HH/4 = 32 float4 per row
    float m0 = g_pm[row], m1 = g_pm[MM + row];
    float l0 = g_pl[row], l1 = g_pl[MM + row];
    float ms = fmaxf(m0, m1);
    float e0 = __expf(m0 - ms), e1 = __expf(m1 - ms);
    float inv = 1.0f / (l0*e0 + l1*e1);
    float4 a = ((const float4*)g_po)[i];
    float4 bv = ((const float4*)(g_po + (size_t)MM*HH))[i];
    float4 r;
    r.x = (a.x*e0 + bv.x*e1) * inv;
    r.y = (a.y*e0 + bv.y*e1) * inv;
    r.z = (a.z*e0 + bv.z*e1) * inv;
    r.w = (a.w*e0 + bv.w*e1) * inv;
    ((float4*)out)[i] = r;
}

// ---------------------------------------------------------------------------
extern "C" void kernel_launch(void* const* d_in, const int* in_sizes, int n_in,
                              void* d_out, int out_size)
{
    const float* x  = (const float*)d_in[0];
    const float* Wq = (const float*)d_in[1];
    const float* Wk = (const float*)d_in[2];
    const float* Wv = (const float*)d_in[3];
    float* out = (float*)d_out;

    static int attr_set = 0;
    const int qkv_smem  = 4 * 128 * QP * 2;  // 73728 B
    const int attn_smem = 4 * 64 * AP * 2;   // 69632 B
    if (!attr_set) {
        cudaFuncSetAttribute(qkv_mma_kernel,
                             cudaFuncAttributeMaxDynamicSharedMemorySize, qkv_smem);
        cudaFuncSetAttribute(attn_kernel,
                             cudaFuncAttributeMaxDynamicSharedMemorySize, attn_smem);
        attr_set = 1;
    }

    convert_x_kernel<<<MM * DD / 4 / 256, 256>>>(x);
    convert_w_kernel<<<dim3(DD * HH / 256, 3), 256>>>(Wq, Wk, Wv);
    qkv_mma_kernel<<<dim3(MM / 128, 3), 256, qkv_smem>>>();
    attn_kernel<<<dim3(TT / 128, BB, 2), 256, attn_smem>>>();
    combine_kernel<<<MM * HH / 4 / 256, 256>>>(out);
}

// round 9
// speedup vs baseline: 1.5379x; 1.0840x over previous
#include <cuda_runtime.h>
#include <cuda_bf16.h>
#include <math.h>
#include <stdint.h>

#define BB 8
#define TT 2048
#define DD 1024
#define HH 128
#define MM (BB*TT)

// ---------------- device-global scratch (allocation-guard safe) ------------
__device__ __nv_bfloat16 g_xhi[MM*DD];
__device__ __nv_bfloat16 g_xlo[MM*DD];
__device__ __nv_bfloat16 g_wthi[3*HH*DD];   // W^T [mat][n][k]
__device__ __nv_bfloat16 g_wtlo[3*HH*DD];
__device__ __nv_bfloat16 g_qhi[MM*HH];      // post-RoPE, pre-scaled by 1/sqrt(H)
__device__ __nv_bfloat16 g_qlo[MM*HH];
__device__ __nv_bfloat16 g_khi[MM*HH];      // post-RoPE
__device__ __nv_bfloat16 g_klo[MM*HH];
__device__ __nv_bfloat16 g_vhi[MM*HH];
__device__ __nv_bfloat16 g_vlo[MM*HH];
// split-KV partials: [z][b*TT+row]
__device__ float g_po[2*MM*HH];
__device__ float g_pm[2*MM];
__device__ float g_pl[2*MM];

// ---------------- PTX helpers (base sm_103-safe) ----------------------------
__device__ __forceinline__ uint32_t smem_u32(const void* p) {
    uint32_t a;
    asm("{ .reg .u64 t; cvta.to.shared.u64 t, %1; cvt.u32.u64 %0, t; }"
        : "=r"(a) : "l"(p));
    return a;
}

__device__ __forceinline__ void cp16(uint32_t saddr, const void* g) {
    asm volatile("cp.async.cg.shared.global [%0], [%1], 16;"
                 :: "r"(saddr), "l"(g) : "memory");
}
__device__ __forceinline__ void cp_commit() {
    asm volatile("cp.async.commit_group;" ::: "memory");
}
__device__ __forceinline__ void cp_wait0() {
    asm volatile("cp.async.wait_group 0;" ::: "memory");
}
__device__ __forceinline__ void cp_wait1() {
    asm volatile("cp.async.wait_group 1;" ::: "memory");
}

__device__ __forceinline__ void ldsm_x4(uint32_t& a0, uint32_t& a1,
                                        uint32_t& a2, uint32_t& a3, uint32_t addr) {
    asm volatile("ldmatrix.sync.aligned.m8n8.x4.shared.b16 {%0,%1,%2,%3}, [%4];"
                 : "=r"(a0), "=r"(a1), "=r"(a2), "=r"(a3) : "r"(addr));
}
__device__ __forceinline__ void ldsm_x2(uint32_t& b0, uint32_t& b1, uint32_t addr) {
    asm volatile("ldmatrix.sync.aligned.m8n8.x2.shared.b16 {%0,%1}, [%2];"
                 : "=r"(b0), "=r"(b1) : "r"(addr));
}
__device__ __forceinline__ void ldsm_x2t(uint32_t& b0, uint32_t& b1, uint32_t addr) {
    asm volatile("ldmatrix.sync.aligned.m8n8.x2.trans.shared.b16 {%0,%1}, [%2];"
                 : "=r"(b0), "=r"(b1) : "r"(addr));
}

__device__ __forceinline__ void mma16816(float* c, const uint32_t* a,
                                         uint32_t b0, uint32_t b1) {
    asm volatile(
        "mma.sync.aligned.m16n8k16.row.col.f32.bf16.bf16.f32 "
        "{%0,%1,%2,%3}, {%4,%5,%6,%7}, {%8,%9}, {%0,%1,%2,%3};"
        : "+f"(c[0]), "+f"(c[1]), "+f"(c[2]), "+f"(c[3])
        : "r"(a[0]), "r"(a[1]), "r"(a[2]), "r"(a[3]), "r"(b0), "r"(b1));
}

__device__ __forceinline__ uint32_t pack_bf16x2(float a, float b) {
    __nv_bfloat162 h(__float2bfloat16(a), __float2bfloat16(b));
    return *reinterpret_cast<uint32_t*>(&h);
}

// ---------------------------------------------------------------------------
// fp32 -> split bf16 conversions
// ---------------------------------------------------------------------------
__global__ __launch_bounds__(256) void convert_x_kernel(const float* __restrict__ x)
{
    int i = blockIdx.x * 256 + threadIdx.x;
    float4 v = ((const float4*)x)[i];
    __nv_bfloat16 h0 = __float2bfloat16(v.x);
    __nv_bfloat16 h1 = __float2bfloat16(v.y);
    __nv_bfloat16 h2 = __float2bfloat16(v.z);
    __nv_bfloat16 h3 = __float2bfloat16(v.w);
    float l0 = v.x - __bfloat162float(h0);
    float l1 = v.y - __bfloat162float(h1);
    float l2 = v.z - __bfloat162float(h2);
    float l3 = v.w - __bfloat162float(h3);
    __nv_bfloat162* ph = (__nv_bfloat162*)g_xhi;
    __nv_bfloat162* pl = (__nv_bfloat162*)g_xlo;
    ph[2*i]   = __nv_bfloat162(h0, h1);
    ph[2*i+1] = __nv_bfloat162(h2, h3);
    pl[2*i]   = __nv_bfloat162(__float2bfloat16(l0), __float2bfloat16(l1));
    pl[2*i+1] = __nv_bfloat162(__float2bfloat16(l2), __float2bfloat16(l3));
}

__global__ __launch_bounds__(256) void convert_w_kernel(
    const float* __restrict__ Wq, const float* __restrict__ Wk,
    const float* __restrict__ Wv)
{
    int mat = blockIdx.y;
    const float* __restrict__ W = (mat == 0) ? Wq : ((mat == 1) ? Wk : Wv);
    int i = blockIdx.x * 256 + threadIdx.x;
    int k = i >> 7;
    int n = i & 127;
    float w = W[i];
    __nv_bfloat16 h = __float2bfloat16(w);
    float lo = w - __bfloat162float(h);
    size_t o = (size_t)mat * HH * DD + (size_t)n * DD + k;
    g_wthi[o] = h;
    g_wtlo[o] = __float2bfloat16(lo);
}

// ---------------------------------------------------------------------------
// QKV projection, cp.async double-buffered split-bf16 mma + RoPE epilogue
// grid=(128,3), 256 threads. smem: 2 buffers x (4 tiles x 128 x QP halves)
// ---------------------------------------------------------------------------
#define QP 72
#define QBUF (4*128*QP)

__global__ __launch_bounds__(256) void qkv_mma_kernel()
{
    extern __shared__ __nv_bfloat16 smq[];

    const int tid = threadIdx.x;
    const int w   = tid >> 5;
    const int lane= tid & 31;
    const int mat = blockIdx.y;
    const int m0  = blockIdx.x * 128;

    const __nv_bfloat16* __restrict__ Xh = g_xhi + (size_t)m0 * DD;
    const __nv_bfloat16* __restrict__ Xl = g_xlo + (size_t)m0 * DD;
    const __nv_bfloat16* __restrict__ Bh = g_wthi + (size_t)mat * HH * DD;
    const __nv_bfloat16* __restrict__ Bl = g_wtlo + (size_t)mat * HH * DD;

    float c[16][4];
#pragma unroll
    for (int nt = 0; nt < 16; nt++)
#pragma unroll
        for (int e = 0; e < 4; e++) c[nt][e] = 0.0f;

    // stage chunk kc into buffer buf
    auto stageq = [&](int buf, int kc) {
        const int kb = kc * 64;
        __nv_bfloat16* base = smq + buf * QBUF;
        const __nv_bfloat16* srcs[4] = {Xh, Xl, Bh, Bl};
#pragma unroll
        for (int t = 0; t < 4; t++) {
#pragma unroll
            for (int itr = 0; itr < 4; itr++) {
                int idx = itr * 256 + tid;
                int row = idx >> 3, seg = idx & 7;
                cp16(smem_u32(base + t*128*QP + row*QP + seg*8),
                     srcs[t] + (size_t)row * DD + kb + seg*8);
            }
        }
    };

    stageq(0, 0);
    cp_commit();

    for (int kc = 0; kc < 16; kc++) {
        if (kc + 1 < 16) { stageq((kc + 1) & 1, kc + 1); cp_commit(); cp_wait1(); }
        else             { cp_wait0(); }
        __syncthreads();

        __nv_bfloat16* base = smq + (kc & 1) * QBUF;
        __nv_bfloat16* sxh = base;
        __nv_bfloat16* sxl = base + 128*QP;
        __nv_bfloat16* swh = base + 2*128*QP;
        __nv_bfloat16* swl = base + 3*128*QP;

        uint32_t ah[4][4], al[4][4];
        {
            int r = w*16 + (lane & 7) + ((lane >> 3) & 1) * 8;
            int cg = ((lane >> 4) & 1) * 8;
#pragma unroll
            for (int kt = 0; kt < 4; kt++) {
                ldsm_x4(ah[kt][0], ah[kt][1], ah[kt][2], ah[kt][3],
                        smem_u32(sxh + r*QP + kt*16 + cg));
                ldsm_x4(al[kt][0], al[kt][1], al[kt][2], al[kt][3],
                        smem_u32(sxl + r*QP + kt*16 + cg));
            }
        }

#pragma unroll
        for (int nt = 0; nt < 16; nt++) {
#pragma unroll
            for (int kt = 0; kt < 4; kt++) {
                int br = nt*8 + (lane & 7);
                int bc = kt*16 + (lane & 8);
                uint32_t b0, b1, e0, e1;
                ldsm_x2(b0, b1, smem_u32(swh + br*QP + bc));
                ldsm_x2(e0, e1, smem_u32(swl + br*QP + bc));
                mma16816(c[nt], ah[kt], b0, b1);
                mma16816(c[nt], al[kt], b0, b1);
                mma16816(c[nt], ah[kt], e0, e1);
            }
        }
        __syncthreads();
    }

    __nv_bfloat16* oh = (mat == 0) ? g_qhi : (mat == 1) ? g_khi : g_vhi;
    __nv_bfloat16* ol = (mat == 0) ? g_qlo : (mat == 1) ? g_klo : g_vlo;
    const float qs = (mat == 0) ? 0.08838834764831845f : 1.0f;

    const int rloc = w*16 + (lane >> 2);
    const int m_lo = m0 + rloc;
    const int m_hi = m_lo + 8;
    const float pos0 = (float)(m_lo & (TT - 1));
    const float pos1 = (float)(m_hi & (TT - 1));

#pragma unroll
    for (int nt = 0; nt < 16; nt++) {
        int col = nt*8 + (lane & 3)*2;
        float e00 = c[nt][0]*qs, e01 = c[nt][1]*qs;
        float e10 = c[nt][2]*qs, e11 = c[nt][3]*qs;
        if (mat < 2) {
            int p = col >> 1;
            float freq = exp2f(-(float)p * (13.287712379549449f / 64.0f));
            float s0, c0v, s1, c1v;
            sincosf(pos0 * freq, &s0, &c0v);
            sincosf(pos1 * freq, &s1, &c1v);
            float t0 = e00*c0v - e01*s0, t1 = e00*s0 + e01*c0v;
            e00 = t0; e01 = t1;
            t0 = e10*c1v - e11*s1; t1 = e10*s1 + e11*c1v;
            e10 = t0; e11 = t1;
        }
        {
            __nv_bfloat16 h0 = __float2bfloat16(e00), h1 = __float2bfloat16(e01);
            *(uint32_t*)(oh + (size_t)m_lo*HH + col) = pack_bf16x2(__bfloat162float(h0), __bfloat162float(h1));
            *(uint32_t*)(ol + (size_t)m_lo*HH + col) =
                pack_bf16x2(e00 - __bfloat162float(h0), e01 - __bfloat162float(h1));
        }
        {
            __nv_bfloat16 h0 = __float2bfloat16(e10), h1 = __float2bfloat16(e11);
            *(uint32_t*)(oh + (size_t)m_hi*HH + col) = pack_bf16x2(__bfloat162float(h0), __bfloat162float(h1));
            *(uint32_t*)(ol + (size_t)m_hi*HH + col) =
                pack_bf16x2(e10 - __bfloat162float(h0), e11 - __bfloat162float(h1));
        }
    }
}

// ---------------------------------------------------------------------------
// Causal flash attention, split-KV z=2 + cp.async double-buffered K/V tiles
// grid=(16,8,2), 256 threads, q-tile 128, k-tile 64.
// smem: 2 buffers x (4 tiles x 64 x AP halves) = 139264 B
// ---------------------------------------------------------------------------
#define AP 136
#define ABUF (4*64*AP)

__global__ __launch_bounds__(256) void attn_kernel()
{
    extern __shared__ __nv_bfloat16 sma[];

    const int tid = threadIdx.x;
    const int w   = tid >> 5;
    const int lane= tid & 31;
    const int b   = blockIdx.y;
    const int z   = blockIdx.z;
    const int i0  = (gridDim.x - 1 - blockIdx.x) * 128;

    const int rloc = w*16 + (lane >> 2);
    const size_t qrow = (size_t)(b*TT + i0 + rloc) * HH;

    uint32_t qh[8][4], ql[8][4];
#pragma unroll
    for (int kt = 0; kt < 8; kt++) {
        int cb = kt*16 + (lane & 3)*2;
        qh[kt][0] = *(const uint32_t*)(g_qhi + qrow + cb);
        qh[kt][1] = *(const uint32_t*)(g_qhi + qrow + 8*HH + cb);
        qh[kt][2] = *(const uint32_t*)(g_qhi + qrow + cb + 8);
        qh[kt][3] = *(const uint32_t*)(g_qhi + qrow + 8*HH + cb + 8);
        ql[kt][0] = *(const uint32_t*)(g_qlo + qrow + cb);
        ql[kt][1] = *(const uint32_t*)(g_qlo + qrow + 8*HH + cb);
        ql[kt][2] = *(const uint32_t*)(g_qlo + qrow + cb + 8);
        ql[kt][3] = *(const uint32_t*)(g_qlo + qrow + 8*HH + cb + 8);
    }

    float o[16][4];
#pragma unroll
    for (int nt = 0; nt < 16; nt++)
#pragma unroll
        for (int e = 0; e < 4; e++) o[nt][e] = 0.0f;
    float mrow0 = -1e30f, mrow1 = -1e30f, l0 = 0.0f, l1 = 0.0f;

    const int ntiles = i0/64 + 2;            // even
    const int htiles = ntiles >> 1;
    const int jt0 = z * htiles;
    const int n = htiles;

    auto stagea = [&](int buf, int jt) {
        const size_t gbase = (size_t)(b*TT + jt*64) * HH;
        __nv_bfloat16* base = sma + buf * ABUF;
        const __nv_bfloat16* srcs[4] = {g_khi + gbase, g_klo + gbase,
                                        g_vhi + gbase, g_vlo + gbase};
#pragma unroll
        for (int t = 0; t < 4; t++) {
#pragma unroll
            for (int itr = 0; itr < 4; itr++) {
                int idx = itr*256 + tid;
                int row = idx >> 4, seg = idx & 15;
                cp16(smem_u32(base + t*64*AP + row*AP + seg*8),
                     srcs[t] + (size_t)row*HH + seg*8);
            }
        }
    };

    stagea(0, jt0);
    cp_commit();

    for (int i = 0; i < n; i++) {
        const int jt = jt0 + i;
        const int j0 = jt * 64;

        if (i + 1 < n) { stagea((i + 1) & 1, jt + 1); cp_commit(); cp_wait1(); }
        else           { cp_wait0(); }
        __syncthreads();

        __nv_bfloat16* base = sma + (i & 1) * ABUF;
        __nv_bfloat16* kh = base;
        __nv_bfloat16* kl = base + 64*AP;
        __nv_bfloat16* vh = base + 2*64*AP;
        __nv_bfloat16* vl = base + 3*64*AP;

        float s[8][4];
#pragma unroll
        for (int nt = 0; nt < 8; nt++)
#pragma unroll
            for (int e = 0; e < 4; e++) s[nt][e] = 0.0f;

#pragma unroll
        for (int nt = 0; nt < 8; nt++) {
#pragma unroll
            for (int kt = 0; kt < 8; kt++) {
                int br = nt*8 + (lane & 7);
                int bc = kt*16 + (lane & 8);
                uint32_t b0, b1, e0, e1;
                ldsm_x2(b0, b1, smem_u32(kh + br*AP + bc));
                ldsm_x2(e0, e1, smem_u32(kl + br*AP + bc));
                mma16816(s[nt], qh[kt], b0, b1);
                mma16816(s[nt], ql[kt], b0, b1);
                mma16816(s[nt], qh[kt], e0, e1);
            }
        }

        if (j0 >= i0) {
            int row0 = i0 + rloc;
            int row1 = row0 + 8;
#pragma unroll
            for (int nt = 0; nt < 8; nt++) {
                int colb = j0 + nt*8 + (lane & 3)*2;
                if (colb     > row0) s[nt][0] = -1e30f;
                if (colb + 1 > row0) s[nt][1] = -1e30f;
                if (colb     > row1) s[nt][2] = -1e30f;
                if (colb + 1 > row1) s[nt][3] = -1e30f;
            }
        }

        float rm0 = -1e30f, rm1 = -1e30f;
#pragma unroll
        for (int nt = 0; nt < 8; nt++) {
            rm0 = fmaxf(rm0, fmaxf(s[nt][0], s[nt][1]));
            rm1 = fmaxf(rm1, fmaxf(s[nt][2], s[nt][3]));
        }
        rm0 = fmaxf(rm0, __shfl_xor_sync(0xffffffffu, rm0, 1));
        rm0 = fmaxf(rm0, __shfl_xor_sync(0xffffffffu, rm0, 2));
        rm1 = fmaxf(rm1, __shfl_xor_sync(0xffffffffu, rm1, 1));
        rm1 = fmaxf(rm1, __shfl_xor_sync(0xffffffffu, rm1, 2));

        float mn0 = fmaxf(mrow0, rm0), mn1 = fmaxf(mrow1, rm1);
        float sc0 = __expf(mrow0 - mn0), sc1 = __expf(mrow1 - mn1);
        mrow0 = mn0; mrow1 = mn1;

        float rs0 = 0.0f, rs1 = 0.0f;
        uint32_t ph[4][4], pl[4][4];
#pragma unroll
        for (int nt = 0; nt < 8; nt++) {
            float p0 = __expf(s[nt][0] - mn0);
            float p1 = __expf(s[nt][1] - mn0);
            float p2 = __expf(s[nt][2] - mn1);
            float p3 = __expf(s[nt][3] - mn1);
            rs0 += p0 + p1;
            rs1 += p2 + p3;
            float h0 = __bfloat162float(__float2bfloat16(p0));
            float h1 = __bfloat162float(__float2bfloat16(p1));
            float h2 = __bfloat162float(__float2bfloat16(p2));
            float h3 = __bfloat162float(__float2bfloat16(p3));
            int kt2 = nt >> 1;
            int hi  = (nt & 1) * 2;
            ph[kt2][hi + 0] = pack_bf16x2(h0, h1);
            ph[kt2][hi + 1] = pack_bf16x2(h2, h3);
            pl[kt2][hi + 0] = pack_bf16x2(p0 - h0, p1 - h1);
            pl[kt2][hi + 1] = pack_bf16x2(p2 - h2, p3 - h3);
        }
        rs0 += __shfl_xor_sync(0xffffffffu, rs0, 1);
        rs0 += __shfl_xor_sync(0xffffffffu, rs0, 2);
        rs1 += __shfl_xor_sync(0xffffffffu, rs1, 1);
        rs1 += __shfl_xor_sync(0xffffffffu, rs1, 2);
        l0 = l0 * sc0 + rs0;
        l1 = l1 * sc1 + rs1;

#pragma unroll
        for (int nt = 0; nt < 16; nt++) {
            o[nt][0] *= sc0; o[nt][1] *= sc0;
            o[nt][2] *= sc1; o[nt][3] *= sc1;
        }
#pragma unroll
        for (int nt = 0; nt < 16; nt++) {
#pragma unroll
            for (int kt2 = 0; kt2 < 4; kt2++) {
                int vr = kt2*16 + (lane & 7) + (lane & 8);
                int vc = nt*8;
                uint32_t b0, b1, e0, e1;
                ldsm_x2t(b0, b1, smem_u32(vh + vr*AP + vc));
                ldsm_x2t(e0, e1, smem_u32(vl + vr*AP + vc));
                mma16816(o[nt], ph[kt2], b0, b1);
                mma16816(o[nt], pl[kt2], b0, b1);
                mma16816(o[nt], ph[kt2], e0, e1);
            }
        }
        __syncthreads();    // protect buffer (i&1) before it is re-staged
    }

    // store unnormalized partials
    const size_t prow = (size_t)z*MM + (size_t)(b*TT + i0 + rloc);
    if ((lane & 3) == 0) {
        g_pm[prow]     = mrow0;  g_pl[prow]     = l0;
        g_pm[prow + 8] = mrow1;  g_pl[prow + 8] = l1;
    }
#pragma unroll
    for (int nt = 0; nt < 16; nt++) {
        int col = nt*8 + (lane & 3)*2;
        *(float2*)(g_po + prow*HH + col)       = make_float2(o[nt][0], o[nt][1]);
        *(float2*)(g_po + (prow + 8)*HH + col) = make_float2(o[nt][2], o[nt][3]);
    }
}

// ---------------------------------------------------------------------------
// combine the two split-KV partials
// ---------------------------------------------------------------------------
__global__ __launch_bounds__(256) void combine_kernel(float* __restrict__ out)
{
    int i = blockIdx.x * 256 + threadIdx.x;
    int row = i >> 5;
    float m0 = g_pm[row], m1 = g_pm[MM + row];
    float l0 = g_pl[row], l1 = g_pl[MM + row];
    float ms = fmaxf(m0, m1);
    float e0 = __expf(m0 - ms), e1 = __expf(m1 - ms);
    float inv = 1.0f / (l0*e0 + l1*e1);
    float4 a = ((const float4*)g_po)[i];
    float4 bv = ((const float4*)(g_po + (size_t)MM*HH))[i];
    float4 r;
    r.x = (a.x*e0 + bv.x*e1) * inv;
    r.y = (a.y*e0 + bv.y*e1) * inv;
    r.z = (a.z*e0 + bv.z*e1) * inv;
    r.w = (a.w*e0 + bv.w*e1) * inv;
    ((float4*)out)[i] = r;
}

// ---------------------------------------------------------------------------
extern "C" void kernel_launch(void* const* d_in, const int* in_sizes, int n_in,
                              void* d_out, int out_size)
{
    const float* x  = (const float*)d_in[0];
    const float* Wq = (const float*)d_in[1];
    const float* Wk = (const float*)d_in[2];
    const float* Wv = (const float*)d_in[3];
    float* out = (float*)d_out;

    static int attr_set = 0;
    const int qkv_smem  = 2 * QBUF * 2;   // 147456 B
    const int attn_smem = 2 * ABUF * 2;   // 139264 B
    if (!attr_set) {
        cudaFuncSetAttribute(qkv_mma_kernel,
                             cudaFuncAttributeMaxDynamicSharedMemorySize, qkv_smem);
        cudaFuncSetAttribute(attn_kernel,
                             cudaFuncAttributeMaxDynamicSharedMemorySize, attn_smem);
        attr_set = 1;
    }

    convert_x_kernel<<<MM * DD / 4 / 256, 256>>>(x);
    convert_w_kernel<<<dim3(DD * HH / 256, 3), 256>>>(Wq, Wk, Wv);
    qkv_mma_kernel<<<dim3(MM / 128, 3), 256, qkv_smem>>>();
    attn_kernel<<<dim3(TT / 128, BB, 2), 256, attn_smem>>>();
    combine_kernel<<<MM * HH / 4 / 256, 256>>>(out);
}

// round 11
// speedup vs baseline: 1.6114x; 1.0478x over previous
#include <cuda_runtime.h>
#include <cuda_bf16.h>
#include <math.h>
#include <stdint.h>

#define BB 8
#define TT 2048
#define DD 1024
#define HH 128
#define MM (BB*TT)

// ---------------- device-global scratch (allocation-guard safe) ------------
__device__ __nv_bfloat16 g_xhi[MM*DD];
__device__ __nv_bfloat16 g_xlo[MM*DD];
__device__ __nv_bfloat16 g_wthi[3*HH*DD];   // W^T [mat][n][k]
__device__ __nv_bfloat16 g_wtlo[3*HH*DD];
__device__ __nv_bfloat16 g_qhi[MM*HH];      // post-RoPE, pre-scaled by 1/sqrt(H)
__device__ __nv_bfloat16 g_qlo[MM*HH];
__device__ __nv_bfloat16 g_khi[MM*HH];      // post-RoPE
__device__ __nv_bfloat16 g_klo[MM*HH];
__device__ __nv_bfloat16 g_vhi[MM*HH];
__device__ __nv_bfloat16 g_vlo[MM*HH];
// split-KV partials: [z][b*TT+row]
__device__ float g_po[2*MM*HH];
__device__ float g_pm[2*MM];
__device__ float g_pl[2*MM];

// ---------------- PTX helpers (base sm_103-safe) ----------------------------
__device__ __forceinline__ uint32_t smem_u32(const void* p) {
    uint32_t a;
    asm("{ .reg .u64 t; cvta.to.shared.u64 t, %1; cvt.u32.u64 %0, t; }"
        : "=r"(a) : "l"(p));
    return a;
}

__device__ __forceinline__ void cp16(uint32_t saddr, const void* g) {
    asm volatile("cp.async.cg.shared.global [%0], [%1], 16;"
                 :: "r"(saddr), "l"(g) : "memory");
}
__device__ __forceinline__ void cp_commit() {
    asm volatile("cp.async.commit_group;" ::: "memory");
}
__device__ __forceinline__ void cp_wait0() {
    asm volatile("cp.async.wait_group 0;" ::: "memory");
}
__device__ __forceinline__ void cp_wait1() {
    asm volatile("cp.async.wait_group 1;" ::: "memory");
}

__device__ __forceinline__ void ldsm_x4(uint32_t& a0, uint32_t& a1,
                                        uint32_t& a2, uint32_t& a3, uint32_t addr) {
    asm volatile("ldmatrix.sync.aligned.m8n8.x4.shared.b16 {%0,%1,%2,%3}, [%4];"
                 : "=r"(a0), "=r"(a1), "=r"(a2), "=r"(a3) : "r"(addr));
}
__device__ __forceinline__ void ldsm_x4t(uint32_t& a0, uint32_t& a1,
                                         uint32_t& a2, uint32_t& a3, uint32_t addr) {
    asm volatile("ldmatrix.sync.aligned.m8n8.x4.trans.shared.b16 {%0,%1,%2,%3}, [%4];"
                 : "=r"(a0), "=r"(a1), "=r"(a2), "=r"(a3) : "r"(addr));
}

__device__ __forceinline__ void mma16816(float* c, const uint32_t* a,
                                         uint32_t b0, uint32_t b1) {
    asm volatile(
        "mma.sync.aligned.m16n8k16.row.col.f32.bf16.bf16.f32 "
        "{%0,%1,%2,%3}, {%4,%5,%6,%7}, {%8,%9}, {%0,%1,%2,%3};"
        : "+f"(c[0]), "+f"(c[1]), "+f"(c[2]), "+f"(c[3])
        : "r"(a[0]), "r"(a[1]), "r"(a[2]), "r"(a[3]), "r"(b0), "r"(b1));
}

__device__ __forceinline__ uint32_t pack_bf16x2(float a, float b) {
    __nv_bfloat162 h(__float2bfloat16(a), __float2bfloat16(b));
    return *reinterpret_cast<uint32_t*>(&h);
}

// ---------------------------------------------------------------------------
// fp32 -> split bf16 conversions
// ---------------------------------------------------------------------------
__global__ __launch_bounds__(256) void convert_x_kernel(const float* __restrict__ x)
{
    int i = blockIdx.x * 256 + threadIdx.x;
    float4 v = ((const float4*)x)[i];
    __nv_bfloat16 h0 = __float2bfloat16(v.x);
    __nv_bfloat16 h1 = __float2bfloat16(v.y);
    __nv_bfloat16 h2 = __float2bfloat16(v.z);
    __nv_bfloat16 h3 = __float2bfloat16(v.w);
    float l0 = v.x - __bfloat162float(h0);
    float l1 = v.y - __bfloat162float(h1);
    float l2 = v.z - __bfloat162float(h2);
    float l3 = v.w - __bfloat162float(h3);
    __nv_bfloat162* ph = (__nv_bfloat162*)g_xhi;
    __nv_bfloat162* pl = (__nv_bfloat162*)g_xlo;
    ph[2*i]   = __nv_bfloat162(h0, h1);
    ph[2*i+1] = __nv_bfloat162(h2, h3);
    pl[2*i]   = __nv_bfloat162(__float2bfloat16(l0), __float2bfloat16(l1));
    pl[2*i+1] = __nv_bfloat162(__float2bfloat16(l2), __float2bfloat16(l3));
}

__global__ __launch_bounds__(256) void convert_w_kernel(
    const float* __restrict__ Wq, const float* __restrict__ Wk,
    const float* __restrict__ Wv)
{
    int mat = blockIdx.y;
    const float* __restrict__ W = (mat == 0) ? Wq : ((mat == 1) ? Wk : Wv);
    int i = blockIdx.x * 256 + threadIdx.x;
    int k = i >> 7;
    int n = i & 127;
    float w = W[i];
    __nv_bfloat16 h = __float2bfloat16(w);
    float lo = w - __bfloat162float(h);
    size_t o = (size_t)mat * HH * DD + (size_t)n * DD + k;
    g_wthi[o] = h;
    g_wtlo[o] = __float2bfloat16(lo);
}

// ---------------------------------------------------------------------------
// QKV projection, cp.async double-buffered split-bf16 mma + RoPE epilogue
// grid=(128,3), 256 threads. smem: 2 buffers x (4 tiles x 128 x QP halves)
// ---------------------------------------------------------------------------
#define QP 72
#define QBUF (4*128*QP)

__global__ __launch_bounds__(256) void qkv_mma_kernel()
{
    extern __shared__ __nv_bfloat16 smq[];

    const int tid = threadIdx.x;
    const int w   = tid >> 5;
    const int lane= tid & 31;
    const int mat = blockIdx.y;
    const int m0  = blockIdx.x * 128;

    const __nv_bfloat16* __restrict__ Xh = g_xhi + (size_t)m0 * DD;
    const __nv_bfloat16* __restrict__ Xl = g_xlo + (size_t)m0 * DD;
    const __nv_bfloat16* __restrict__ Bh = g_wthi + (size_t)mat * HH * DD;
    const __nv_bfloat16* __restrict__ Bl = g_wtlo + (size_t)mat * HH * DD;

    float c[16][4];
#pragma unroll
    for (int nt = 0; nt < 16; nt++)
#pragma unroll
        for (int e = 0; e < 4; e++) c[nt][e] = 0.0f;

    auto stageq = [&](int buf, int kc) {
        const int kb = kc * 64;
        __nv_bfloat16* base = smq + buf * QBUF;
        const __nv_bfloat16* srcs[4] = {Xh, Xl, Bh, Bl};
#pragma unroll
        for (int t = 0; t < 4; t++) {
#pragma unroll
            for (int itr = 0; itr < 4; itr++) {
                int idx = itr * 256 + tid;
                int row = idx >> 3, seg = idx & 7;
                cp16(smem_u32(base + t*128*QP + row*QP + seg*8),
                     srcs[t] + (size_t)row * DD + kb + seg*8);
            }
        }
    };

    stageq(0, 0);
    cp_commit();

    for (int kc = 0; kc < 16; kc++) {
        if (kc + 1 < 16) { stageq((kc + 1) & 1, kc + 1); cp_commit(); cp_wait1(); }
        else             { cp_wait0(); }
        __syncthreads();

        __nv_bfloat16* base = smq + (kc & 1) * QBUF;
        __nv_bfloat16* sxh = base;
        __nv_bfloat16* sxl = base + 128*QP;
        __nv_bfloat16* swh = base + 2*128*QP;
        __nv_bfloat16* swl = base + 3*128*QP;

        uint32_t ah[4][4], al[4][4];
        {
            int r = w*16 + (lane & 7) + ((lane >> 3) & 1) * 8;
            int cg = ((lane >> 4) & 1) * 8;
#pragma unroll
            for (int kt = 0; kt < 4; kt++) {
                ldsm_x4(ah[kt][0], ah[kt][1], ah[kt][2], ah[kt][3],
                        smem_u32(sxh + r*QP + kt*16 + cg));
                ldsm_x4(al[kt][0], al[kt][1], al[kt][2], al[kt][3],
                        smem_u32(sxl + r*QP + kt*16 + cg));
            }
        }

        // B fragments: pairs of n-tiles via ldmatrix.x4
        const int brr = (lane & 7) + ((lane >> 4) & 1) * 8;
        const int bcc = (lane & 8);
#pragma unroll
        for (int nt2 = 0; nt2 < 8; nt2++) {
#pragma unroll
            for (int kt = 0; kt < 4; kt++) {
                int br = nt2*16 + brr;
                int bc = kt*16 + bcc;
                uint32_t b4[4], e4[4];
                ldsm_x4(b4[0], b4[1], b4[2], b4[3], smem_u32(swh + br*QP + bc));
                ldsm_x4(e4[0], e4[1], e4[2], e4[3], smem_u32(swl + br*QP + bc));
                mma16816(c[2*nt2],   ah[kt], b4[0], b4[1]);
                mma16816(c[2*nt2],   al[kt], b4[0], b4[1]);
                mma16816(c[2*nt2],   ah[kt], e4[0], e4[1]);
                mma16816(c[2*nt2+1], ah[kt], b4[2], b4[3]);
                mma16816(c[2*nt2+1], al[kt], b4[2], b4[3]);
                mma16816(c[2*nt2+1], ah[kt], e4[2], e4[3]);
            }
        }
        __syncthreads();
    }

    __nv_bfloat16* oh = (mat == 0) ? g_qhi : (mat == 1) ? g_khi : g_vhi;
    __nv_bfloat16* ol = (mat == 0) ? g_qlo : (mat == 1) ? g_klo : g_vlo;
    const float qs = (mat == 0) ? 0.08838834764831845f : 1.0f;

    const int rloc = w*16 + (lane >> 2);
    const int m_lo = m0 + rloc;
    const int m_hi = m_lo + 8;
    const float pos0 = (float)(m_lo & (TT - 1));
    const float pos1 = (float)(m_hi & (TT - 1));

#pragma unroll
    for (int nt = 0; nt < 16; nt++) {
        int col = nt*8 + (lane & 3)*2;
        float e00 = c[nt][0]*qs, e01 = c[nt][1]*qs;
        float e10 = c[nt][2]*qs, e11 = c[nt][3]*qs;
        if (mat < 2) {
            int p = col >> 1;
            float freq = exp2f(-(float)p * (13.287712379549449f / 64.0f));
            float s0, c0v, s1, c1v;
            sincosf(pos0 * freq, &s0, &c0v);
            sincosf(pos1 * freq, &s1, &c1v);
            float t0 = e00*c0v - e01*s0, t1 = e00*s0 + e01*c0v;
            e00 = t0; e01 = t1;
            t0 = e10*c1v - e11*s1; t1 = e10*s1 + e11*c1v;
            e10 = t0; e11 = t1;
        }
        {
            __nv_bfloat16 h0 = __float2bfloat16(e00), h1 = __float2bfloat16(e01);
            *(uint32_t*)(oh + (size_t)m_lo*HH + col) = pack_bf16x2(__bfloat162float(h0), __bfloat162float(h1));
            *(uint32_t*)(ol + (size_t)m_lo*HH + col) =
                pack_bf16x2(e00 - __bfloat162float(h0), e01 - __bfloat162float(h1));
        }
        {
            __nv_bfloat16 h0 = __float2bfloat16(e10), h1 = __float2bfloat16(e11);
            *(uint32_t*)(oh + (size_t)m_hi*HH + col) = pack_bf16x2(__bfloat162float(h0), __bfloat162float(h1));
            *(uint32_t*)(ol + (size_t)m_hi*HH + col) =
                pack_bf16x2(e10 - __bfloat162float(h0), e11 - __bfloat162float(h1));
        }
    }
}

// ---------------------------------------------------------------------------
// Causal flash attention, split-KV z=2 + cp.async double-buffered K/V tiles
// grid=(16,8,2), 256 threads, q-tile 128, k-tile 64.
// smem: 2 buffers x (4 tiles x 64 x AP halves) = 139264 B
// ---------------------------------------------------------------------------
#define AP 136
#define ABUF (4*64*AP)

__global__ __launch_bounds__(256) void attn_kernel()
{
    extern __shared__ __nv_bfloat16 sma[];

    const int tid = threadIdx.x;
    const int w   = tid >> 5;
    const int lane= tid & 31;
    const int b   = blockIdx.y;
    const int z   = blockIdx.z;
    const int i0  = (gridDim.x - 1 - blockIdx.x) * 128;

    const int rloc = w*16 + (lane >> 2);
    const size_t qrow = (size_t)(b*TT + i0 + rloc) * HH;

    uint32_t qh[8][4], ql[8][4];
#pragma unroll
    for (int kt = 0; kt < 8; kt++) {
        int cb = kt*16 + (lane & 3)*2;
        qh[kt][0] = *(const uint32_t*)(g_qhi + qrow + cb);
        qh[kt][1] = *(const uint32_t*)(g_qhi + qrow + 8*HH + cb);
        qh[kt][2] = *(const uint32_t*)(g_qhi + qrow + cb + 8);
        qh[kt][3] = *(const uint32_t*)(g_qhi + qrow + 8*HH + cb + 8);
        ql[kt][0] = *(const uint32_t*)(g_qlo + qrow + cb);
        ql[kt][1] = *(const uint32_t*)(g_qlo + qrow + 8*HH + cb);
        ql[kt][2] = *(const uint32_t*)(g_qlo + qrow + cb + 8);
        ql[kt][3] = *(const uint32_t*)(g_qlo + qrow + 8*HH + cb + 8);
    }

    float o[16][4];
#pragma unroll
    for (int nt = 0; nt < 16; nt++)
#pragma unroll
        for (int e = 0; e < 4; e++) o[nt][e] = 0.0f;
    float mrow0 = -1e30f, mrow1 = -1e30f, l0 = 0.0f, l1 = 0.0f;

    const int ntiles = i0/64 + 2;            // even
    const int htiles = ntiles >> 1;
    const int jt0 = z * htiles;
    const int n = htiles;

    auto stagea = [&](int buf, int jt) {
        const size_t gbase = (size_t)(b*TT + jt*64) * HH;
        __nv_bfloat16* base = sma + buf * ABUF;
        const __nv_bfloat16* srcs[4] = {g_khi + gbase, g_klo + gbase,
                                        g_vhi + gbase, g_vlo + gbase};
#pragma unroll
        for (int t = 0; t < 4; t++) {
#pragma unroll
            for (int itr = 0; itr < 4; itr++) {
                int idx = itr*256 + tid;
                int row = idx >> 4, seg = idx & 15;
                cp16(smem_u32(base + t*64*AP + row*AP + seg*8),
                     srcs[t] + (size_t)row*HH + seg*8);
            }
        }
    };

    stagea(0, jt0);
    cp_commit();

    const int brr = (lane & 7) + ((lane >> 4) & 1) * 8;   // B-frag row offset
    const int bcc = (lane & 8);                            // B-frag col offset
    const int vrr = (lane & 7) + (lane & 8);               // V-frag row offset
    const int vcc = ((lane >> 4) & 1) * 8;                 // V-frag col offset

    for (int i = 0; i < n; i++) {
        const int jt = jt0 + i;
        const int j0 = jt * 64;

        if (i + 1 < n) { stagea((i + 1) & 1, jt + 1); cp_commit(); cp_wait1(); }
        else           { cp_wait0(); }
        __syncthreads();

        __nv_bfloat16* base = sma + (i & 1) * ABUF;
        __nv_bfloat16* kh = base;
        __nv_bfloat16* kl = base + 64*AP;
        __nv_bfloat16* vh = base + 2*64*AP;
        __nv_bfloat16* vl = base + 3*64*AP;

        float s[8][4];
#pragma unroll
        for (int nt = 0; nt < 8; nt++)
#pragma unroll
            for (int e = 0; e < 4; e++) s[nt][e] = 0.0f;

        // S = Q K^T: n-tile pairs via ldmatrix.x4
#pragma unroll
        for (int nt2 = 0; nt2 < 4; nt2++) {
#pragma unroll
            for (int kt = 0; kt < 8; kt++) {
                int br = nt2*16 + brr;
                int bc = kt*16 + bcc;
                uint32_t b4[4], e4[4];
                ldsm_x4(b4[0], b4[1], b4[2], b4[3], smem_u32(kh + br*AP + bc));
                ldsm_x4(e4[0], e4[1], e4[2], e4[3], smem_u32(kl + br*AP + bc));
                mma16816(s[2*nt2],   qh[kt], b4[0], b4[1]);
                mma16816(s[2*nt2],   ql[kt], b4[0], b4[1]);
                mma16816(s[2*nt2],   qh[kt], e4[0], e4[1]);
                mma16816(s[2*nt2+1], qh[kt], b4[2], b4[3]);
                mma16816(s[2*nt2+1], ql[kt], b4[2], b4[3]);
                mma16816(s[2*nt2+1], qh[kt], e4[2], e4[3]);
            }
        }

        if (j0 >= i0) {
            int row0 = i0 + rloc;
            int row1 = row0 + 8;
#pragma unroll
            for (int nt = 0; nt < 8; nt++) {
                int colb = j0 + nt*8 + (lane & 3)*2;
                if (colb     > row0) s[nt][0] = -1e30f;
                if (colb + 1 > row0) s[nt][1] = -1e30f;
                if (colb     > row1) s[nt][2] = -1e30f;
                if (colb + 1 > row1) s[nt][3] = -1e30f;
            }
        }

        float rm0 = -1e30f, rm1 = -1e30f;
#pragma unroll
        for (int nt = 0; nt < 8; nt++) {
            rm0 = fmaxf(rm0, fmaxf(s[nt][0], s[nt][1]));
            rm1 = fmaxf(rm1, fmaxf(s[nt][2], s[nt][3]));
        }
        rm0 = fmaxf(rm0, __shfl_xor_sync(0xffffffffu, rm0, 1));
        rm0 = fmaxf(rm0, __shfl_xor_sync(0xffffffffu, rm0, 2));
        rm1 = fmaxf(rm1, __shfl_xor_sync(0xffffffffu, rm1, 1));
        rm1 = fmaxf(rm1, __shfl_xor_sync(0xffffffffu, rm1, 2));

        float mn0 = fmaxf(mrow0, rm0), mn1 = fmaxf(mrow1, rm1);
        float sc0 = __expf(mrow0 - mn0), sc1 = __expf(mrow1 - mn1);
        mrow0 = mn0; mrow1 = mn1;

        float rs0 = 0.0f, rs1 = 0.0f;
        uint32_t ph[4][4], pl[4][4];
#pragma unroll
        for (int nt = 0; nt < 8; nt++) {
            float p0 = __expf(s[nt][0] - mn0);
            float p1 = __expf(s[nt][1] - mn0);
            float p2 = __expf(s[nt][2] - mn1);
            float p3 = __expf(s[nt][3] - mn1);
            rs0 += p0 + p1;
            rs1 += p2 + p3;
            float h0 = __bfloat162float(__float2bfloat16(p0));
            float h1 = __bfloat162float(__float2bfloat16(p1));
            float h2 = __bfloat162float(__float2bfloat16(p2));
            float h3 = __bfloat162float(__float2bfloat16(p3));
            int kt2 = nt >> 1;
            int hi  = (nt & 1) * 2;
            ph[kt2][hi + 0] = pack_bf16x2(h0, h1);
            ph[kt2][hi + 1] = pack_bf16x2(h2, h3);
            pl[kt2][hi + 0] = pack_bf16x2(p0 - h0, p1 - h1);
            pl[kt2][hi + 1] = pack_bf16x2(p2 - h2, p3 - h3);
        }
        rs0 += __shfl_xor_sync(0xffffffffu, rs0, 1);
        rs0 += __shfl_xor_sync(0xffffffffu, rs0, 2);
        rs1 += __shfl_xor_sync(0xffffffffu, rs1, 1);
        rs1 += __shfl_xor_sync(0xffffffffu, rs1, 2);
        l0 = l0 * sc0 + rs0;
        l1 = l1 * sc1 + rs1;

#pragma unroll
        for (int nt = 0; nt < 16; nt++) {
            o[nt][0] *= sc0; o[nt][1] *= sc0;
            o[nt][2] *= sc1; o[nt][3] *= sc1;
        }
        // O += P V: output n-tile pairs via ldmatrix.x4.trans
#pragma unroll
        for (int nt2 = 0; nt2 < 8; nt2++) {
#pragma unroll
            for (int kt2 = 0; kt2 < 4; kt2++) {
                int vr = kt2*16 + vrr;
                int vc = nt2*16 + vcc;
                uint32_t b4[4], e4[4];
                ldsm_x4t(b4[0], b4[1], b4[2], b4[3], smem_u32(vh + vr*AP + vc));
                ldsm_x4t(e4[0], e4[1], e4[2], e4[3], smem_u32(vl + vr*AP + vc));
                mma16816(o[2*nt2],   ph[kt2], b4[0], b4[1]);
                mma16816(o[2*nt2],   pl[kt2], b4[0], b4[1]);
                mma16816(o[2*nt2],   ph[kt2], e4[0], e4[1]);
                mma16816(o[2*nt2+1], ph[kt2], b4[2], b4[3]);
                mma16816(o[2*nt2+1], pl[kt2], b4[2], b4[3]);
                mma16816(o[2*nt2+1], ph[kt2], e4[2], e4[3]);
            }
        }
        __syncthreads();    // protect buffer (i&1) before it is re-staged
    }

    // store unnormalized partials
    const size_t prow = (size_t)z*MM + (size_t)(b*TT + i0 + rloc);
    if ((lane & 3) == 0) {
        g_pm[prow]     = mrow0;  g_pl[prow]     = l0;
        g_pm[prow + 8] = mrow1;  g_pl[prow + 8] = l1;
    }
#pragma unroll
    for (int nt = 0; nt < 16; nt++) {
        int col = nt*8 + (lane & 3)*2;
        *(float2*)(g_po + prow*HH + col)       = make_float2(o[nt][0], o[nt][1]);
        *(float2*)(g_po + (prow + 8)*HH + col) = make_float2(o[nt][2], o[nt][3]);
    }
}

// ---------------------------------------------------------------------------
// combine the two split-KV partials
// ---------------------------------------------------------------------------
__global__ __launch_bounds__(256) void combine_kernel(float* __restrict__ out)
{
    int i = blockIdx.x * 256 + threadIdx.x;
    int row = i >> 5;
    float m0 = g_pm[row], m1 = g_pm[MM + row];
    float l0 = g_pl[row], l1 = g_pl[MM + row];
    float ms = fmaxf(m0, m1);
    float e0 = __expf(m0 - ms), e1 = __expf(m1 - ms);
    float inv = 1.0f / (l0*e0 + l1*e1);
    float4 a = ((const float4*)g_po)[i];
    float4 bv = ((const float4*)(g_po + (size_t)MM*HH))[i];
    float4 r;
    r.x = (a.x*e0 + bv.x*e1) * inv;
    r.y = (a.y*e0 + bv.y*e1) * inv;
    r.z = (a.z*e0 + bv.z*e1) * inv;
    r.w = (a.w*e0 + bv.w*e1) * inv;
    ((float4*)out)[i] = r;
}

// ---------------------------------------------------------------------------
extern "C" void kernel_launch(void* const* d_in, const int* in_sizes, int n_in,
                              void* d_out, int out_size)
{
    const float* x  = (const float*)d_in[0];
    const float* Wq = (const float*)d_in[1];
    const float* Wk = (const float*)d_in[2];
    const float* Wv = (const float*)d_in[3];
    float* out = (float*)d_out;

    static int attr_set = 0;
    const int qkv_smem  = 2 * QBUF * 2;   // 147456 B
    const int attn_smem = 2 * ABUF * 2;   // 139264 B
    if (!attr_set) {
        cudaFuncSetAttribute(qkv_mma_kernel,
                             cudaFuncAttributeMaxDynamicSharedMemorySize, qkv_smem);
        cudaFuncSetAttribute(attn_kernel,
                             cudaFuncAttributeMaxDynamicSharedMemorySize, attn_smem);
        attr_set = 1;
    }

    convert_x_kernel<<<MM * DD / 4 / 256, 256>>>(x);
    convert_w_kernel<<<dim3(DD * HH / 256, 3), 256>>>(Wq, Wk, Wv);
    qkv_mma_kernel<<<dim3(MM / 128, 3), 256, qkv_smem>>>();
    attn_kernel<<<dim3(TT / 128, BB, 2), 256, attn_smem>>>();
    combine_kernel<<<MM * HH / 4 / 256, 256>>>(out);
}